// round 6
// baseline (speedup 1.0000x reference)
#include <cuda_runtime.h>
#include <cstdint>

// Problem constants
#define B_ROWS   2048
#define DIM_IN   4096
#define DIM_OUT  4096
#define KW       128          // DIM_IN / 32 packed words

// Scratch (allocation-free rule: __device__ globals)
__device__ uint32_t g_xp[B_ROWS * KW];    // 1 MB: packed x, row-major [b][w]
__device__ uint32_t g_mp[DIM_OUT * KW];   // 2 MB: packed masks, [j][w]

// ---------------------------------------------------------------------------
// Kernel 1: pack x (int32 0/1) -> bits. One warp per output word via ballot.
// ---------------------------------------------------------------------------
__global__ void pack_x_kernel(const int* __restrict__ x) {
    int g    = blockIdx.x * blockDim.x + threadIdx.x;
    int warp = g >> 5;
    int lane = g & 31;
    // warp = b*KW + w
    int b = warp >> 7;          // /128
    int w = warp & 127;
    int v = x[b * DIM_IN + w * 32 + lane];
    unsigned m = __ballot_sync(0xffffffffu, v != 0);
    if (lane == 0) g_xp[warp] = m;
}

// ---------------------------------------------------------------------------
// Kernel 2: pack masks -> g_mp[j][w].
// masks stored as 4-byte elements (int32 0/1 OR float32 0.0/1.0); in both
// encodings "nonzero word" == true, so read as uint32_t and test != 0.
// Thread per (j, w); consecutive threads -> consecutive j (coalesced).
// ---------------------------------------------------------------------------
__global__ void pack_m_kernel(const uint32_t* __restrict__ m) {
    int g = blockIdx.x * blockDim.x + threadIdx.x;   // [0, DIM_OUT*KW)
    int w = g >> 12;            // / DIM_OUT
    int j = g & (DIM_OUT - 1);
    const uint32_t* p = m + (size_t)(w * 32) * DIM_OUT + j;
    unsigned word = 0;
#pragma unroll
    for (int i = 0; i < 32; i++) {
        word |= ((unsigned)(p[(size_t)i * DIM_OUT] != 0u)) << i;
    }
    g_mp[j * KW + w] = word;
}

// ---------------------------------------------------------------------------
// Kernel 3: XNOR-popcount GEMM + threshold epilogue (float32 output).
// Block: 64x64 outputs, 256 threads, 4x4 register tile per thread.
// ---------------------------------------------------------------------------
#define BM 64
#define BN 64
#define CW 16
#define TM 4
#define TN 4

__global__ __launch_bounds__(256)
void xnor_gemm_kernel(const int* __restrict__ thr, float* __restrict__ out) {
    __shared__ uint32_t xs[BM][CW + 1];
    __shared__ uint32_t ms[BN][CW + 1];

    const int tid  = threadIdx.x;
    const int tx   = tid & 15;      // 16 col-groups
    const int ty   = tid >> 4;      // 16 row-groups
    const int row0 = blockIdx.y * BM;
    const int col0 = blockIdx.x * BN;

    int acc[TM][TN] = {};

    for (int w0 = 0; w0 < KW; w0 += CW) {
        // Load BM*CW + BN*CW = 2048 words with 256 threads (4+4 each)
#pragma unroll
        for (int i = 0; i < 4; i++) {
            int idx = tid + i * 256;
            int r = idx / CW;
            int w = idx % CW;
            xs[r][w] = g_xp[(row0 + r) * KW + w0 + w];
            ms[r][w] = g_mp[(col0 + r) * KW + w0 + w];
        }
        __syncthreads();

#pragma unroll
        for (int w = 0; w < CW; w++) {
            uint32_t a[TM], b[TN];
#pragma unroll
            for (int i = 0; i < TM; i++) a[i] = xs[ty * TM + i][w];
#pragma unroll
            for (int j = 0; j < TN; j++) b[j] = ms[tx * TN + j][w];
#pragma unroll
            for (int i = 0; i < TM; i++)
#pragma unroll
                for (int j = 0; j < TN; j++)
                    acc[i][j] += __popc(a[i] ^ b[j]);
        }
        __syncthreads();
    }

    // Epilogue: sums = DIM_IN - hamming; out = (sums > thr[c]) ? 1.0f : 0.0f
    int t[TN];
    const int cbase = col0 + tx * TN;
#pragma unroll
    for (int j = 0; j < TN; j++) t[j] = thr[cbase + j];

#pragma unroll
    for (int i = 0; i < TM; i++) {
        int r = row0 + ty * TM + i;
        float4 v;
        v.x = ((DIM_IN - acc[i][0]) > t[0]) ? 1.0f : 0.0f;
        v.y = ((DIM_IN - acc[i][1]) > t[1]) ? 1.0f : 0.0f;
        v.z = ((DIM_IN - acc[i][2]) > t[2]) ? 1.0f : 0.0f;
        v.w = ((DIM_IN - acc[i][3]) > t[3]) ? 1.0f : 0.0f;
        *reinterpret_cast<float4*>(out + (size_t)r * DIM_OUT + cbase) = v;
    }
}

// ---------------------------------------------------------------------------
extern "C" void kernel_launch(void* const* d_in, const int* in_sizes, int n_in,
                              void* d_out, int out_size) {
    const int*      x    = (const int*)d_in[0];       // (B, DIM_IN) int32
    const uint32_t* mask = (const uint32_t*)d_in[1];  // (DIM_IN, DIM_OUT), 4-byte 0/1
    const int*      thr  = (const int*)d_in[2];       // (DIM_OUT,) int32
    float*          out  = (float*)d_out;             // (B, DIM_OUT) float 0/1

    // 1) pack x: B*KW warps
    {
        int total_threads = B_ROWS * KW * 32;
        pack_x_kernel<<<total_threads / 256, 256>>>(x);
    }
    // 2) pack masks: DIM_OUT*KW threads
    {
        int total_threads = DIM_OUT * KW;
        pack_m_kernel<<<total_threads / 256, 256>>>(mask);
    }
    // 3) GEMM + epilogue
    {
        dim3 grid(DIM_OUT / BN, B_ROWS / BM);
        xnor_gemm_kernel<<<grid, 256>>>(thr, out);
    }
}

// round 7
// speedup vs baseline: 1.2742x; 1.2742x over previous
#include <cuda_runtime.h>
#include <cstdint>

// Problem constants
#define B_ROWS   2048
#define DIM_IN   4096
#define DIM_OUT  4096
#define KW       128          // DIM_IN / 32 packed words

// Scratch (allocation-free rule: __device__ globals)
__device__ uint32_t g_xp[B_ROWS * KW];     // packed x, row-major [b][w]
__device__ uint32_t g_mp[KW * DIM_OUT];    // packed masks, TRANSPOSED [w][j]

// ---------------------------------------------------------------------------
// Kernel 1: pack x (int32 0/1) -> bits. One THREAD per output word.
// Reads 8 x int4 (32 values) per thread; values are exactly 0/1.
// ---------------------------------------------------------------------------
__global__ void pack_x_kernel(const int4* __restrict__ x4) {
    int t = blockIdx.x * blockDim.x + threadIdx.x;   // word index [0, B_ROWS*KW)
    const int4* p = x4 + (size_t)t * 8;
    unsigned w = 0;
#pragma unroll
    for (int i = 0; i < 8; i++) {
        int4 v = p[i];
        w |= ((unsigned)v.x) << (4 * i + 0);
        w |= ((unsigned)v.y) << (4 * i + 1);
        w |= ((unsigned)v.z) << (4 * i + 2);
        w |= ((unsigned)v.w) << (4 * i + 3);
    }
    g_xp[t] = w;
}

// ---------------------------------------------------------------------------
// Kernel 2: pack masks -> g_mp[w][j]  (TRANSPOSED: coalesced stores).
// masks are 4-byte elements; nonzero == true. Coalesced loads across j.
// ---------------------------------------------------------------------------
__global__ void pack_m_kernel(const uint32_t* __restrict__ m) {
    int g = blockIdx.x * blockDim.x + threadIdx.x;   // [0, KW*DIM_OUT)
    int w = g >> 12;            // / DIM_OUT
    int j = g & (DIM_OUT - 1);
    const uint32_t* p = m + (size_t)(w * 32) * DIM_OUT + j;
    unsigned word = 0;
#pragma unroll
    for (int i = 0; i < 32; i++) {
        word |= ((unsigned)(p[(size_t)i * DIM_OUT] != 0u)) << i;
    }
    g_mp[w * DIM_OUT + j] = word;    // coalesced store
}

// ---------------------------------------------------------------------------
// Kernel 3: XNOR-popcount GEMM with CSA (carry-save adder) compression.
// 8 XOR words -> 4 POPCs (weights 1,2,2,4). Block 64x64, 256 threads, 4x4 tile.
// Masks in smem transposed [w][j] so b-loads are conflict-free uint4.
// ---------------------------------------------------------------------------
#define BM 64
#define BN 64
#define CW 16
#define XS_STRIDE (CW + 4)     // 20 words (16B-aligned rows)
#define MS_STRIDE (BN + 4)     // 68 words (16B-aligned rows)

__global__ __launch_bounds__(256)
void xnor_gemm_kernel(const int* __restrict__ thr, float* __restrict__ out) {
    __shared__ uint32_t xs[BM][XS_STRIDE];   // [row][w]
    __shared__ uint32_t ms[CW][MS_STRIDE];   // [w][col]  (transposed)

    const int tid  = threadIdx.x;
    const int tx   = tid & 15;      // 16 col-groups
    const int ty   = tid >> 4;      // 16 row-groups
    const int row0 = blockIdx.y * BM;
    const int col0 = blockIdx.x * BN;

    // global->smem load assignment (one uint4 each per tile)
    const int xr = tid >> 2;            // 0..63
    const int xw = (tid & 3) * 4;       // 0,4,8,12
    const int mw = tid >> 4;            // 0..15
    const int mj = (tid & 15) * 4;      // 0..60

    int acc[4][4] = {};

    for (int w0 = 0; w0 < KW; w0 += CW) {
        {
            uint4 v = *reinterpret_cast<const uint4*>(&g_xp[(row0 + xr) * KW + w0 + xw]);
            *reinterpret_cast<uint4*>(&xs[xr][xw]) = v;
        }
        {
            uint4 v = *reinterpret_cast<const uint4*>(&g_mp[(w0 + mw) * DIM_OUT + col0 + mj]);
            *reinterpret_cast<uint4*>(&ms[mw][mj]) = v;
        }
        __syncthreads();

#pragma unroll
        for (int g = 0; g < CW / 8; g++) {
            uint32_t a[4][8];
            uint32_t b[4][8];
#pragma unroll
            for (int i = 0; i < 4; i++) {
                uint4 v0 = *reinterpret_cast<const uint4*>(&xs[ty * 4 + i][g * 8]);
                uint4 v1 = *reinterpret_cast<const uint4*>(&xs[ty * 4 + i][g * 8 + 4]);
                a[i][0] = v0.x; a[i][1] = v0.y; a[i][2] = v0.z; a[i][3] = v0.w;
                a[i][4] = v1.x; a[i][5] = v1.y; a[i][6] = v1.z; a[i][7] = v1.w;
            }
#pragma unroll
            for (int w = 0; w < 8; w++) {
                uint4 v = *reinterpret_cast<const uint4*>(&ms[g * 8 + w][tx * 4]);
                b[0][w] = v.x; b[1][w] = v.y; b[2][w] = v.z; b[3][w] = v.w;
            }
#pragma unroll
            for (int i = 0; i < 4; i++)
#pragma unroll
                for (int j = 0; j < 4; j++) {
                    uint32_t x0 = a[i][0] ^ b[j][0], x1 = a[i][1] ^ b[j][1];
                    uint32_t x2 = a[i][2] ^ b[j][2], x3 = a[i][3] ^ b[j][3];
                    uint32_t x4 = a[i][4] ^ b[j][4], x5 = a[i][5] ^ b[j][5];
                    uint32_t x6 = a[i][6] ^ b[j][6], x7 = a[i][7] ^ b[j][7];
                    // level 1: two full adders + one half adder
                    uint32_t s1 = x0 ^ x1 ^ x2, c1 = (x0 & x1) | (x2 & (x0 | x1));
                    uint32_t s2 = x3 ^ x4 ^ x5, c2 = (x3 & x4) | (x5 & (x3 | x4));
                    uint32_t s3 = x6 ^ x7,      c3 = x6 & x7;
                    // level 2
                    uint32_t S  = s1 ^ s2 ^ s3, C  = (s1 & s2) | (s3 & (s1 | s2));
                    uint32_t S2 = c1 ^ c2 ^ c3, C2 = (c1 & c2) | (c3 & (c1 | c2));
                    // sum popc(x0..x7) = popc(S) + 2(popc(C)+popc(S2)) + 4 popc(C2)
                    acc[i][j] += __popc(S) + 2 * (__popc(C) + __popc(S2))
                               + 4 * __popc(C2);
                }
        }
        __syncthreads();
    }

    // Epilogue: matches = DIM_IN - acc; out = matches > thr  <=>  acc < DIM_IN - thr
    const int cbase = col0 + tx * 4;
    int u[4];
#pragma unroll
    for (int j = 0; j < 4; j++) u[j] = DIM_IN - thr[cbase + j];

#pragma unroll
    for (int i = 0; i < 4; i++) {
        int r = row0 + ty * 4 + i;
        float4 v;
        v.x = (acc[i][0] < u[0]) ? 1.0f : 0.0f;
        v.y = (acc[i][1] < u[1]) ? 1.0f : 0.0f;
        v.z = (acc[i][2] < u[2]) ? 1.0f : 0.0f;
        v.w = (acc[i][3] < u[3]) ? 1.0f : 0.0f;
        *reinterpret_cast<float4*>(out + (size_t)r * DIM_OUT + cbase) = v;
    }
}

// ---------------------------------------------------------------------------
extern "C" void kernel_launch(void* const* d_in, const int* in_sizes, int n_in,
                              void* d_out, int out_size) {
    const int4*     x4   = (const int4*)d_in[0];      // (B, DIM_IN) int32 0/1
    const uint32_t* mask = (const uint32_t*)d_in[1];  // (DIM_IN, DIM_OUT), 4-byte 0/1
    const int*      thr  = (const int*)d_in[2];       // (DIM_OUT,) int32
    float*          out  = (float*)d_out;             // (B, DIM_OUT) float 0/1

    // 1) pack x: one thread per word
    pack_x_kernel<<<(B_ROWS * KW) / 256, 256>>>(x4);
    // 2) pack masks (transposed output)
    pack_m_kernel<<<(KW * DIM_OUT) / 256, 256>>>(mask);
    // 3) CSA GEMM + epilogue
    {
        dim3 grid(DIM_OUT / BN, B_ROWS / BM);
        xnor_gemm_kernel<<<grid, 256>>>(thr, out);
    }
}